// round 13
// baseline (speedup 1.0000x reference)
#include <cuda_runtime.h>
#include <cuda_fp16.h>
#include <cstdint>

// ---------------------------------------------------------------------------
// BinarizeLinear: out[32768,512] = x[32768,512] @ sign(W)[512,512]  (fp32)
// fp16 mma.sync m16n8k16 at the legacy-HMMA issue ceiling (~512 MAC/cyc/SM).
// A loaded as RAW FP32 via cp.async (no separate convert pass); fragments
// built with LDS.64 + cvt.rn.f16x2 in the slack under the HMMA ceiling.
// B = sign(W)^T fp16 (ldsm4, swizzled). BK=32, 3 stages, 2 CTAs/SM.
// ---------------------------------------------------------------------------

#define NT 32768
#define KD 512
#define ND 512

#define BM 128
#define BN 128
#define BK 32                         // elements per stage (fp32 A / fp16 B)
#define STAGES 3
#define N_ITERS (KD / BK)             // 16

#define A_STRIDE   160                // 128B data + 32B pad (bank-conflict-free LDS.64)
#define A_STAGE    (128 * A_STRIDE)   // 20480
#define B_STAGE    16384              // 128 rows x 128B (64B data, swizzle-proven)
#define SLOT_BYTES (A_STAGE + B_STAGE)         // 36864
#define SMEM_BYTES (STAGES * SLOT_BYTES)       // 110592 -> 2 CTAs/SM (221KB)

// sign(W)^T as fp16, [N][K] (K contiguous); 0.5 MB, L2-resident
__device__ __half g_BTh[ND * KD];

// ---------------------------------------------------------------------------
__device__ __forceinline__ uint32_t su32(const void* p) {
    uint32_t a;
    asm("{ .reg .u64 t; cvta.to.shared.u64 t, %1; cvt.u32.u64 %0, t; }"
        : "=r"(a) : "l"(p));
    return a;
}

__device__ __forceinline__ void cp16(uint32_t s, const void* g) {
    asm volatile("cp.async.cg.shared.global [%0], [%1], 16;" :: "r"(s), "l"(g));
}

__device__ __forceinline__ uint32_t pack_h2(float lo, float hi) {
    uint32_t u;
    asm("cvt.rn.f16x2.f32 %0, %1, %2;" : "=r"(u) : "f"(hi), "f"(lo));
    return u;
}

__device__ __forceinline__ void ldsm4(uint32_t& r0, uint32_t& r1,
                                      uint32_t& r2, uint32_t& r3, uint32_t a) {
    asm volatile("ldmatrix.sync.aligned.m8n8.x4.shared.b16 {%0,%1,%2,%3}, [%4];"
                 : "=r"(r0), "=r"(r1), "=r"(r2), "=r"(r3) : "r"(a));
}

__device__ __forceinline__ void mma_f16(float* d, const uint32_t* a, const uint32_t* b) {
    asm volatile(
        "mma.sync.aligned.m16n8k16.row.col.f32.f16.f16.f32 "
        "{%0,%1,%2,%3}, {%4,%5,%6,%7}, {%8,%9}, {%0,%1,%2,%3};"
        : "+f"(d[0]), "+f"(d[1]), "+f"(d[2]), "+f"(d[3])
        : "r"(a[0]), "r"(a[1]), "r"(a[2]), "r"(a[3]), "r"(b[0]), "r"(b[1]));
}

// ---------------------------------------------------------------------------
// Pre-kernel: g_BTh[n*512 + k] = (half)sign(W[k*512 + n])
// ---------------------------------------------------------------------------
__global__ void __launch_bounds__(256)
sign_transpose_kernel(const float* __restrict__ W) {
    int idx = blockIdx.x * 256 + threadIdx.x;
    int k = idx >> 9;
    int n = idx & 511;
    float w = W[idx];
    unsigned short h = (w > 0.0f) ? (unsigned short)0x3C00
                     : ((w < 0.0f) ? (unsigned short)0xBC00 : (unsigned short)0);
    reinterpret_cast<unsigned short*>(g_BTh)[n * KD + k] = h;
}

// ---------------------------------------------------------------------------
// Producer: one stage = A 128x32 fp32 (160B-padded rows, linear) +
//                       B 128x32 fp16 (128B rows, XOR swizzle).
// A: 1024 x 16B chunks, B: 512 x 16B chunks; 256 threads; one commit.
// ---------------------------------------------------------------------------
__device__ __forceinline__ void produce(uint32_t sb, int slot, int k0,
                                        int m_base, int n_base,
                                        const float* __restrict__ x, int tid) {
    uint32_t abase = sb + (uint32_t)slot * SLOT_BYTES;
    uint32_t bbase = abase + A_STAGE;
    #pragma unroll
    for (int i = 0; i < 4; ++i) {
        int c   = tid + i * 256;       // 0..1023
        int row = c >> 3;              // 0..127
        int kc  = c & 7;               // 16B chunk (4 fp32)
        cp16(abase + (uint32_t)row * A_STRIDE + (uint32_t)kc * 16u,
             x + (size_t)(m_base + row) * KD + k0 + kc * 4);
    }
    #pragma unroll
    for (int i = 0; i < 2; ++i) {
        int c   = tid + i * 256;       // 0..511
        int row = c >> 2;              // 0..127
        int kc  = c & 3;               // 16B chunk (8 halves)
        uint32_t off = (uint32_t)row * 128u
                     + (((uint32_t)kc * 16u) ^ (((uint32_t)row & 7u) << 4));
        cp16(bbase + off, g_BTh + (size_t)(n_base + row) * KD + k0 + kc * 8);
    }
    asm volatile("cp.async.commit_group;" ::: "memory");
}

// ---------------------------------------------------------------------------
__global__ void __launch_bounds__(256, 2)
gemm_kernel(const float* __restrict__ x, float* __restrict__ out) {
    extern __shared__ char smem[];
    const uint32_t sb = su32(smem);
    const int tid  = threadIdx.x;
    const int wid  = tid >> 5;
    const int lane = tid & 31;
    const int wr   = wid & 3;          // warp row: m offset wr*32
    const int wc   = wid >> 2;         // warp col: n offset wc*64
    const int g    = lane >> 2;
    const int t    = lane & 3;

    const int ntile  = blockIdx.x & 3;          // adjacent CTAs share A panel
    const int mtile  = blockIdx.x >> 2;
    const int m_base = mtile * BM;
    const int n_base = ntile * BN;

    // A (fp32, padded rows, no swizzle): per-thread fragment byte base
    const uint32_t a_byte = (uint32_t)(wr * 32 + g) * A_STRIDE + (uint32_t)t * 8u;
    // B (fp16, 128B rows, XOR swizzle) ldmatrix addressing
    const uint32_t swz    = ((uint32_t)(lane & 7)) << 4;
    const uint32_t khalf  = ((uint32_t)(lane >> 4)) << 4;   // 0 or 16 bytes
    const uint32_t b_off  = (uint32_t)(wc * 64 + (lane & 15)) * 128u;

    float d[2][8][4];
    #pragma unroll
    for (int mt = 0; mt < 2; ++mt)
        #pragma unroll
        for (int nt = 0; nt < 8; ++nt)
            #pragma unroll
            for (int q = 0; q < 4; ++q) d[mt][nt][q] = 0.0f;

    produce(sb, 0, 0,  m_base, n_base, x, tid);
    produce(sb, 1, BK, m_base, n_base, x, tid);

    for (int it = 0; it < N_ITERS; ++it) {
        if (it < N_ITERS - 1) asm volatile("cp.async.wait_group 1;" ::: "memory");
        else                  asm volatile("cp.async.wait_group 0;" ::: "memory");
        __syncthreads();

        if (it + 2 < N_ITERS)
            produce(sb, (it + 2) % STAGES, (it + 2) * BK, m_base, n_base, x, tid);

        const char*    Asm = smem + (size_t)(it % STAGES) * SLOT_BYTES;
        const uint32_t Bsm = sb + (uint32_t)(it % STAGES) * SLOT_BYTES + A_STAGE;

        #pragma unroll
        for (int kk = 0; kk < 2; ++kk) {          // two k16 chunks per BK=32
            // ---- A fragments: LDS.64 fp32 pairs -> f16x2 packs ----
            // rows: mt*16 + {0,8}; k: kk*16 + {2t,2t+1} and +8
            const char* ab = Asm + a_byte + kk * 64;
            uint32_t a[2][4];
            #pragma unroll
            for (int mt = 0; mt < 2; ++mt) {
                const char* p = ab + mt * (16 * A_STRIDE);
                float2 v0 = *reinterpret_cast<const float2*>(p);
                float2 v1 = *reinterpret_cast<const float2*>(p + 8 * A_STRIDE);
                float2 v2 = *reinterpret_cast<const float2*>(p + 32);
                float2 v3 = *reinterpret_cast<const float2*>(p + 8 * A_STRIDE + 32);
                a[mt][0] = pack_h2(v0.x, v0.y);
                a[mt][1] = pack_h2(v1.x, v1.y);
                a[mt][2] = pack_h2(v2.x, v2.y);
                a[mt][3] = pack_h2(v3.x, v3.y);
            }

            // ---- B fragments: ldsm4 over 16 n-rows x 16 k-halves ----
            const uint32_t kb = ((uint32_t)kk * 32u + khalf) ^ swz;
            uint32_t b[8][2];
            #pragma unroll
            for (int j = 0; j < 4; ++j) {
                ldsm4(b[2 * j][0], b[2 * j + 1][0], b[2 * j][1], b[2 * j + 1][1],
                      Bsm + b_off + (uint32_t)j * 2048u + kb);
            }

            #pragma unroll
            for (int mt = 0; mt < 2; ++mt)
                #pragma unroll
                for (int nt = 0; nt < 8; ++nt)
                    mma_f16(d[mt][nt], a[mt], b[nt]);
        }
    }

    // Epilogue: register -> global float2 stores
    #pragma unroll
    for (int mt = 0; mt < 2; ++mt) {
        const int r0 = m_base + wr * 32 + mt * 16 + g;
        #pragma unroll
        for (int nt = 0; nt < 8; ++nt) {
            const int c = n_base + wc * 64 + nt * 8 + t * 2;
            *reinterpret_cast<float2*>(out + (size_t)r0 * ND + c) =
                make_float2(d[mt][nt][0], d[mt][nt][1]);
            *reinterpret_cast<float2*>(out + (size_t)(r0 + 8) * ND + c) =
                make_float2(d[mt][nt][2], d[mt][nt][3]);
        }
    }
}

// ---------------------------------------------------------------------------
extern "C" void kernel_launch(void* const* d_in, const int* in_sizes, int n_in,
                              void* d_out, int out_size) {
    const float* x = (const float*)d_in[0];   // [32768, 512]
    const float* W = (const float*)d_in[1];   // [512, 512]
    float* out = (float*)d_out;               // [32768, 512]
    (void)in_sizes; (void)n_in; (void)out_size;

    cudaFuncSetAttribute(gemm_kernel,
                         cudaFuncAttributeMaxDynamicSharedMemorySize, SMEM_BYTES);

    sign_transpose_kernel<<<(KD * ND) / 256, 256>>>(W);
    gemm_kernel<<<(NT / BM) * (ND / BN), 256, SMEM_BYTES>>>(x, out);
}

// round 14
// speedup vs baseline: 1.1072x; 1.1072x over previous
#include <cuda_runtime.h>
#include <cuda_fp16.h>
#include <cstdint>

// ---------------------------------------------------------------------------
// BinarizeLinear: out[32768,512] = x[32768,512] @ sign(W)[512,512]  (fp32)
// fp16 mma.sync m16n8k16 at the legacy issue ceiling. NO x-convert pass:
// A streamed as raw fp32 via cp.async (288B padded rows), fragments built
// with prefetched LDS.64 + cvt.rn.f16x2 hidden under the HMMA trains.
// B = sign(W)^T fp16 (ldsm4, swizzled). BK=64, 2 stages, 2 CTAs/SM.
// ---------------------------------------------------------------------------

#define NT 32768
#define KD 512
#define ND 512

#define BM 128
#define BN 128
#define BK 64                         // elements per stage
#define STAGES 2
#define N_ITERS (KD / BK)             // 8

#define A_STRIDE   288                // 256B fp32 data + 32B pad (LDS.64 conflict-free)
#define A_STAGE    (128 * A_STRIDE)   // 36864
#define B_STAGE    16384              // 128 rows x 128B (swizzled fp16)
#define SLOT_BYTES (A_STAGE + B_STAGE)       // 53248
#define SMEM_BYTES (STAGES * SLOT_BYTES)     // 106496 -> 2 CTAs/SM (208KB)

// sign(W)^T as fp16, [N][K] (K contiguous); 0.5 MB, L2-resident
__device__ __half g_BTh[ND * KD];

// ---------------------------------------------------------------------------
__device__ __forceinline__ uint32_t su32(const void* p) {
    uint32_t a;
    asm("{ .reg .u64 t; cvta.to.shared.u64 t, %1; cvt.u32.u64 %0, t; }"
        : "=r"(a) : "l"(p));
    return a;
}

__device__ __forceinline__ void cp16(uint32_t s, const void* g) {
    asm volatile("cp.async.cg.shared.global [%0], [%1], 16;" :: "r"(s), "l"(g));
}

__device__ __forceinline__ uint32_t pack_h2(float lo, float hi) {
    uint32_t u;
    asm("cvt.rn.f16x2.f32 %0, %1, %2;" : "=r"(u) : "f"(hi), "f"(lo));
    return u;
}

__device__ __forceinline__ void ldsm4(uint32_t& r0, uint32_t& r1,
                                      uint32_t& r2, uint32_t& r3, uint32_t a) {
    asm volatile("ldmatrix.sync.aligned.m8n8.x4.shared.b16 {%0,%1,%2,%3}, [%4];"
                 : "=r"(r0), "=r"(r1), "=r"(r2), "=r"(r3) : "r"(a));
}

__device__ __forceinline__ void mma_f16(float* d, const uint32_t* a, const uint32_t* b) {
    asm volatile(
        "mma.sync.aligned.m16n8k16.row.col.f32.f16.f16.f32 "
        "{%0,%1,%2,%3}, {%4,%5,%6,%7}, {%8,%9}, {%0,%1,%2,%3};"
        : "+f"(d[0]), "+f"(d[1]), "+f"(d[2]), "+f"(d[3])
        : "r"(a[0]), "r"(a[1]), "r"(a[2]), "r"(a[3]), "r"(b[0]), "r"(b[1]));
}

// ---------------------------------------------------------------------------
// Pre-kernel: g_BTh[n*512 + k] = (half)sign(W[k*512 + n])
// ---------------------------------------------------------------------------
__global__ void __launch_bounds__(256)
sign_transpose_kernel(const float* __restrict__ W) {
    int idx = blockIdx.x * 256 + threadIdx.x;
    int k = idx >> 9;
    int n = idx & 511;
    float w = W[idx];
    unsigned short h = (w > 0.0f) ? (unsigned short)0x3C00
                     : ((w < 0.0f) ? (unsigned short)0xBC00 : (unsigned short)0);
    reinterpret_cast<unsigned short*>(g_BTh)[n * KD + k] = h;
}

// ---------------------------------------------------------------------------
// Producer: one stage = A 128x64 fp32 (288B rows) + B 128x64h (swizzled).
// A: 2048 chunks, B: 1024 chunks (16B each); 256 threads; one commit.
// ---------------------------------------------------------------------------
__device__ __forceinline__ void produce(uint32_t sb, int slot, int k0,
                                        int m_base, int n_base,
                                        const float* __restrict__ x, int tid) {
    uint32_t abase = sb + (uint32_t)slot * SLOT_BYTES;
    uint32_t bbase = abase + A_STAGE;
    #pragma unroll
    for (int i = 0; i < 8; ++i) {
        int c   = tid + i * 256;       // 0..2047
        int row = c >> 4;              // 0..127
        int kc  = c & 15;              // 16B chunk (4 fp32)
        cp16(abase + (uint32_t)row * A_STRIDE + (uint32_t)kc * 16u,
             x + (size_t)(m_base + row) * KD + k0 + kc * 4);
    }
    #pragma unroll
    for (int i = 0; i < 4; ++i) {
        int c   = tid + i * 256;       // 0..1023
        int row = c >> 3;              // 0..127
        int kc  = c & 7;               // 16B chunk (8 halves)
        uint32_t off = (uint32_t)row * 128u
                     + (((uint32_t)kc * 16u) ^ (((uint32_t)row & 7u) << 4));
        cp16(bbase + off, g_BTh + (size_t)(n_base + row) * KD + k0 + kc * 8);
    }
    asm volatile("cp.async.commit_group;" ::: "memory");
}

// ---------------------------------------------------------------------------
// A float loads for one kk (k16 chunk): rows (wr*32 + mt*16 + {g, g+8}),
// k bytes kk*64 + t*8 (+32 for the k-hi half).
// ---------------------------------------------------------------------------
__device__ __forceinline__ void loadA(float2 v[2][4], const char* Asm,
                                      uint32_t a_byte, int kk) {
    const char* ab = Asm + a_byte + kk * 64;
    #pragma unroll
    for (int mt = 0; mt < 2; ++mt) {
        const char* p = ab + mt * (16 * A_STRIDE);
        v[mt][0] = *reinterpret_cast<const float2*>(p);
        v[mt][1] = *reinterpret_cast<const float2*>(p + 8 * A_STRIDE);
        v[mt][2] = *reinterpret_cast<const float2*>(p + 32);
        v[mt][3] = *reinterpret_cast<const float2*>(p + 8 * A_STRIDE + 32);
    }
}

// ---------------------------------------------------------------------------
__global__ void __launch_bounds__(256, 2)
gemm_kernel(const float* __restrict__ x, float* __restrict__ out) {
    extern __shared__ char smem[];
    const uint32_t sb = su32(smem);
    const int tid  = threadIdx.x;
    const int wid  = tid >> 5;
    const int lane = tid & 31;
    const int wr   = wid & 3;          // warp row: m offset wr*32
    const int wc   = wid >> 2;         // warp col: n offset wc*64
    const int g    = lane >> 2;
    const int t    = lane & 3;

    const int ntile  = blockIdx.x & 3;          // adjacent CTAs share A panel
    const int mtile  = blockIdx.x >> 2;
    const int m_base = mtile * BM;
    const int n_base = ntile * BN;

    // A fp32 fragment base: row wr*32+g, byte col t*8
    const uint32_t a_byte = (uint32_t)(wr * 32 + g) * A_STRIDE + (uint32_t)t * 8u;
    // B fp16 ldmatrix addressing (swizzled 128B rows)
    const uint32_t swz    = ((uint32_t)(lane & 7)) << 4;
    const uint32_t khalf  = ((uint32_t)(lane >> 4)) << 4;
    const uint32_t b_off  = (uint32_t)(wc * 64 + (lane & 15)) * 128u;

    float d[2][8][4];
    #pragma unroll
    for (int mt = 0; mt < 2; ++mt)
        #pragma unroll
        for (int nt = 0; nt < 8; ++nt)
            #pragma unroll
            for (int q = 0; q < 4; ++q) d[mt][nt][q] = 0.0f;

    produce(sb, 0, 0,  m_base, n_base, x, tid);
    produce(sb, 1, BK, m_base, n_base, x, tid);

    for (int it = 0; it < N_ITERS; ++it) {
        if (it < N_ITERS - 1) asm volatile("cp.async.wait_group 1;" ::: "memory");
        else                  asm volatile("cp.async.wait_group 0;" ::: "memory");
        __syncthreads();

        const int      slot = it % STAGES;
        const char*    Asm  = smem + (size_t)slot * SLOT_BYTES;
        const uint32_t Bsm  = sb + (uint32_t)slot * SLOT_BYTES + A_STAGE;

        float2 v[2][4];
        loadA(v, Asm, a_byte, 0);

        #pragma unroll
        for (int kk = 0; kk < 4; ++kk) {
            // Pack current kk's A fragments
            uint32_t a[2][4];
            #pragma unroll
            for (int mt = 0; mt < 2; ++mt)
                #pragma unroll
                for (int q = 0; q < 4; ++q)
                    a[mt][q] = pack_h2(v[mt][q].x, v[mt][q].y);

            // Prefetch next kk's floats (LDS latency hides under MMAs)
            if (kk < 3) loadA(v, Asm, a_byte, kk + 1);

            const uint32_t kb = ((uint32_t)kk * 32u + khalf) ^ swz;
            uint32_t b[8][2];
            #pragma unroll
            for (int j = 0; j < 4; ++j) {
                ldsm4(b[2 * j][0], b[2 * j + 1][0], b[2 * j][1], b[2 * j + 1][1],
                      Bsm + b_off + (uint32_t)j * 2048u + kb);
            }

            #pragma unroll
            for (int mt = 0; mt < 2; ++mt)
                #pragma unroll
                for (int nt = 0; nt < 8; ++nt)
                    mma_f16(d[mt][nt], a[mt], b[nt]);
        }

        // Refill the slot we just consumed (guard with a barrier first)
        if (it + 2 < N_ITERS) {
            __syncthreads();
            produce(sb, slot, (it + 2) * BK, m_base, n_base, x, tid);
        }
    }

    // Epilogue: register -> global float2 stores
    #pragma unroll
    for (int mt = 0; mt < 2; ++mt) {
        const int r0 = m_base + wr * 32 + mt * 16 + g;
        #pragma unroll
        for (int nt = 0; nt < 8; ++nt) {
            const int c = n_base + wc * 64 + nt * 8 + t * 2;
            *reinterpret_cast<float2*>(out + (size_t)r0 * ND + c) =
                make_float2(d[mt][nt][0], d[mt][nt][1]);
            *reinterpret_cast<float2*>(out + (size_t)(r0 + 8) * ND + c) =
                make_float2(d[mt][nt][2], d[mt][nt][3]);
        }
    }
}

// ---------------------------------------------------------------------------
extern "C" void kernel_launch(void* const* d_in, const int* in_sizes, int n_in,
                              void* d_out, int out_size) {
    const float* x = (const float*)d_in[0];   // [32768, 512]
    const float* W = (const float*)d_in[1];   // [512, 512]
    float* out = (float*)d_out;               // [32768, 512]
    (void)in_sizes; (void)n_in; (void)out_size;

    cudaFuncSetAttribute(gemm_kernel,
                         cudaFuncAttributeMaxDynamicSharedMemorySize, SMEM_BYTES);

    sign_transpose_kernel<<<(KD * ND) / 256, 256>>>(W);
    gemm_kernel<<<(NT / BM) * (ND / BN), 256, SMEM_BYTES>>>(x, out);
}